// round 2
// baseline (speedup 1.0000x reference)
#include <cuda_runtime.h>
#include <cuda_bf16.h>
#include <cstdint>

// GraphSAGE layer: out = relu(concat(x, mean_neigh(x)) @ W + b)
// N=100000 nodes, d=64, E=1250000 edges, W [128,64], b [64], out [N,64] fp32.

#define N_NODES 100000
#define N_EDGES 1250000
#define DIM     64
#define DIM4    16          // DIM / 4 (float4 words per row)
#define NPB     32          // nodes per block in the GEMM kernel
#define XA_PAD  132         // padded row stride (floats) for x_aggr tile: bank-conflict-free

// Scratch (no cudaMalloc allowed): neighbor accumulator + degree counts + dtype flag
__device__ float4 g_neigh4[N_NODES * DIM4];
__device__ float  g_cnt[N_NODES];
__device__ int    g_is64;

// ---------------------------------------------------------------------------
// Kernel 1: zero scratch + detect edge_index dtype (int64 vs int32)
// ---------------------------------------------------------------------------
__global__ void k_zero(const long long* __restrict__ ei) {
    int i = blockIdx.x * blockDim.x + threadIdx.x;
    if (i < N_NODES * DIM4) g_neigh4[i] = make_float4(0.f, 0.f, 0.f, 0.f);
    if (i < N_NODES) g_cnt[i] = 0.f;
    if (i == 0) {
        // Probe first 4 values interpreted as int64. True int64 data: all in [0, N).
        // int32 data read as int64 combines two indices -> huge value unless the
        // high word happens to be 0 (prob ~1e-5 each; all 4 ~1e-20).
        bool ok = true;
        #pragma unroll
        for (int k = 0; k < 4; k++) {
            long long v = ei[k];
            if (v < 0 || v >= (long long)N_NODES) ok = false;
        }
        g_is64 = ok ? 1 : 0;
    }
}

// ---------------------------------------------------------------------------
// Kernel 2: scatter-add neighbor features. 16 lanes per edge (one float4 each),
// 2 edges per warp. Vector reductions (red.global.add.v4.f32) to L2.
// ---------------------------------------------------------------------------
__global__ void __launch_bounds__(256) k_edges(const long long* __restrict__ ei,
                                               const float4* __restrict__ x4) {
    int t    = blockIdx.x * blockDim.x + threadIdx.x;
    int warp = t >> 5;
    int lane = t & 31;
    int e0   = warp * 2;                 // first edge of this warp
    if (e0 >= N_EDGES) return;
    int sub = lane >> 4;                 // which of the 2 edges
    int p   = lane & 15;                 // float4 slot within the row

    int row, col;
    if (g_is64) {
        // int64 layout: rows at [0, E), cols at [E, 2E)
        longlong2 rp = ((const longlong2*)ei)[e0 >> 1];               // uniform per warp
        longlong2 cp = ((const longlong2*)(ei + N_EDGES))[e0 >> 1];
        row = (int)(sub ? rp.y : rp.x);
        col = (int)(sub ? cp.y : cp.x);
    } else {
        const int* e32 = (const int*)ei;
        int2 rp = ((const int2*)e32)[e0 >> 1];
        int2 cp = ((const int2*)(e32 + N_EDGES))[e0 >> 1];
        row = sub ? rp.y : rp.x;
        col = sub ? cp.y : cp.x;
    }

    float4 v = x4[row * DIM4 + p];       // coalesced 256B gather (L2-resident x)
    float* dst = (float*)(g_neigh4 + col * DIM4 + p);
    asm volatile("red.global.add.v4.f32 [%0], {%1, %2, %3, %4};"
                 :: "l"(dst), "f"(v.x), "f"(v.y), "f"(v.z), "f"(v.w)
                 : "memory");
    if (p == 0) {
        asm volatile("red.global.add.f32 [%0], %1;"
                     :: "l"(&g_cnt[col]), "f"(1.0f) : "memory");
    }
}

// ---------------------------------------------------------------------------
// Kernel 3: per-node GEMM + bias + relu.
//   Block = 256 threads, 32 nodes. Shared: W [128][64] + x_aggr tile [32][132].
//   8 threads per node, 8 outputs each. Conflict-free LDS by construction.
// ---------------------------------------------------------------------------
#define SMEM_OUT (128 * 64 * 4 + NPB * XA_PAD * 4)

__global__ void __launch_bounds__(256) k_out(const float4* __restrict__ x4,
                                             const float*  __restrict__ W,
                                             const float*  __restrict__ b,
                                             float*        __restrict__ out) {
    extern __shared__ float sm[];
    float* sW = sm;                      // [128][64]
    float* sX = sm + 128 * 64;           // [NPB][XA_PAD]
    int tid   = threadIdx.x;
    int nbase = blockIdx.x * NPB;

    // Stage W (32KB), coalesced
    for (int i = tid; i < 128 * 64 / 4; i += 256)
        ((float4*)sW)[i] = ((const float4*)W)[i];

    // Stage x rows + mean-scaled neighbor rows
    for (int i = tid; i < NPB * 2 * DIM4; i += 256) {
        int node_l = i >> 5;             // 0..31
        int f4     = i & 31;             // 0..15 -> x, 16..31 -> neigh
        int node   = nbase + node_l;
        float4 v;
        if (f4 < DIM4) {
            v = x4[node * DIM4 + f4];
        } else {
            v = g_neigh4[node * DIM4 + (f4 - DIM4)];
            float inv = 1.0f / fmaxf(g_cnt[node], 1.0f);
            v.x *= inv; v.y *= inv; v.z *= inv; v.w *= inv;
        }
        *(float4*)(sX + node_l * XA_PAD + f4 * 4) = v;
    }
    __syncthreads();

    int node_l = tid >> 3;               // 0..31
    int jg     = (tid & 7) * 8;          // output column group
    const float* xa = sX + node_l * XA_PAD;

    float acc[8];
    #pragma unroll
    for (int j = 0; j < 8; j++) acc[j] = 0.f;

    #pragma unroll 4
    for (int k = 0; k < 128; k += 4) {
        float4 a = *(const float4*)(xa + k);
        #pragma unroll
        for (int kk = 0; kk < 4; kk++) {
            float av = (&a.x)[kk];
            const float4* wr = (const float4*)(sW + (k + kk) * 64 + jg);
            float4 w0 = wr[0];
            float4 w1 = wr[1];
            acc[0] += av * w0.x;  acc[1] += av * w0.y;
            acc[2] += av * w0.z;  acc[3] += av * w0.w;
            acc[4] += av * w1.x;  acc[5] += av * w1.y;
            acc[6] += av * w1.z;  acc[7] += av * w1.w;
        }
    }

    float4 b0 = *(const float4*)(b + jg);
    float4 b1 = *(const float4*)(b + jg + 4);
    float4 o0, o1;
    o0.x = fmaxf(acc[0] + b0.x, 0.f);  o0.y = fmaxf(acc[1] + b0.y, 0.f);
    o0.z = fmaxf(acc[2] + b0.z, 0.f);  o0.w = fmaxf(acc[3] + b0.w, 0.f);
    o1.x = fmaxf(acc[4] + b1.x, 0.f);  o1.y = fmaxf(acc[5] + b1.y, 0.f);
    o1.z = fmaxf(acc[6] + b1.z, 0.f);  o1.w = fmaxf(acc[7] + b1.w, 0.f);

    int node = nbase + node_l;
    *(float4*)(out + node * DIM + jg)     = o0;
    *(float4*)(out + node * DIM + jg + 4) = o1;
}

// ---------------------------------------------------------------------------
extern "C" void kernel_launch(void* const* d_in, const int* in_sizes, int n_in,
                              void* d_out, int out_size) {
    const float*     x  = (const float*)d_in[0];
    const long long* ei = (const long long*)d_in[1];
    const float*     W  = (const float*)d_in[2];
    const float*     b  = (const float*)d_in[3];
    float*           out = (float*)d_out;

    // 1) zero scratch + dtype probe
    k_zero<<<(N_NODES * DIM4 + 255) / 256, 256>>>(ei);

    // 2) scatter-add: 16 threads per edge -> E*16 threads total (exact grid)
    int edge_threads = N_EDGES * 16;
    k_edges<<<edge_threads / 256, 256>>>(ei, (const float4*)x);

    // 3) fused mean + GEMM + bias + relu
    static_assert(N_NODES % NPB == 0, "grid must tile exactly");
    cudaFuncSetAttribute(k_out, cudaFuncAttributeMaxDynamicSharedMemorySize, SMEM_OUT);
    k_out<<<N_NODES / NPB, 256, SMEM_OUT>>>((const float4*)x, W, b, out);
}

// round 6
// speedup vs baseline: 1.3941x; 1.3941x over previous
#include <cuda_runtime.h>
#include <cuda_bf16.h>
#include <cstdint>

// GraphSAGE layer: out = relu(concat(x, mean_neigh(x)) @ W + b)
// N=100000 nodes, d=64, E=1250000 edges, W [128,64], b [64], out [N,64] fp32.

#define N_NODES 100000
#define N_EDGES 1250000
#define DIM     64
#define DIM4    16              // DIM / 4 (float4 words per row)
#define EDGE_GROUPS (N_EDGES / 4)   // 312500, exact
#define NPB     64              // nodes per block in the GEMM kernel
#define XA_PAD  132             // padded row stride (floats) for x_aggr tile

// Scratch (no cudaMalloc allowed)
__device__ float4 g_neigh4[N_NODES * DIM4];
__device__ float  g_cnt[N_NODES];
__device__ int    g_is64;

__device__ __forceinline__ uint32_t smem_u32(const void* p) {
    return (uint32_t)__cvta_generic_to_shared(p);
}

#define FMA2(d, a, b, c) \
    asm("fma.rn.f32x2 %0, %1, %2, %3;" : "=l"(d) : "l"(a), "l"(b), "l"(c))

#define PACK2(d, f) \
    asm("mov.b64 %0, {%1, %1};" : "=l"(d) : "r"(__float_as_uint(f)))

// ---------------------------------------------------------------------------
// Kernel 1: zero scratch + detect edge_index dtype (int64 vs int32)
// ---------------------------------------------------------------------------
__global__ void k_zero(const long long* __restrict__ ei) {
    int i = blockIdx.x * blockDim.x + threadIdx.x;
    if (i < N_NODES * DIM4) g_neigh4[i] = make_float4(0.f, 0.f, 0.f, 0.f);
    if (i < N_NODES) g_cnt[i] = 0.f;
    if (i == 0) {
        bool ok = true;
        #pragma unroll
        for (int k = 0; k < 4; k++) {
            long long v = ei[k];
            if (v < 0 || v >= (long long)N_NODES) ok = false;
        }
        g_is64 = ok ? 1 : 0;
    }
}

// ---------------------------------------------------------------------------
// Kernel 2: scatter-add via TMA bulk-reduce. Each warp stages 4 edge rows
// (256B each) in shared, then issues cp.reduce.async.bulk.add.f32 per edge.
// One 256B reduce op per edge instead of 16 scalar-issued red.v4 requests.
// ---------------------------------------------------------------------------
__global__ void __launch_bounds__(256) k_edges(const long long* __restrict__ ei,
                                               const float4* __restrict__ x4) {
    __shared__ float4 stage[8][2][4][DIM4];   // [warp][buf][edge][f4] = 16KB
    int tid  = threadIdx.x;
    int w    = tid >> 5;
    int lane = tid & 31;
    int gw   = blockIdx.x * 8 + w;
    int totalWarps = gridDim.x * 8;
    bool is64 = (g_is64 != 0);
    const int* e32 = (const int*)ei;

    int p  = lane & 15;          // f4 slot within a row
    int e0 = lane >> 4;          // edge 0..1 for slot set A
    int e1 = e0 + 2;             // edge 2..3 for slot set B

    int it = 0;
    for (int g = gw; g < EDGE_GROUPS; g += totalWarps, ++it) {
        int buf = it & 1;
        // Gate buffer reuse: allow 1 outstanding group per issuing lane
        if (lane < 4)
            asm volatile("cp.async.bulk.wait_group.read 1;" ::: "memory");
        __syncwarp();

        int eb = 4 * g;
        int r0, r1;
        if (is64) { r0 = (int)ei[eb + e0];  r1 = (int)ei[eb + e1]; }
        else      { r0 = e32[eb + e0];      r1 = e32[eb + e1]; }

        stage[w][buf][e0][p] = x4[r0 * DIM4 + p];
        stage[w][buf][e1][p] = x4[r1 * DIM4 + p];
        __syncwarp();

        if (lane < 4) {
            int c;
            if (is64) c = (int)ei[N_EDGES + eb + lane];
            else      c = e32[N_EDGES + eb + lane];
            asm volatile("fence.proxy.async.shared::cta;" ::: "memory");
            uint32_t saddr = smem_u32(&stage[w][buf][lane][0]);
            float* dst = (float*)(g_neigh4 + c * DIM4);
            asm volatile(
                "cp.reduce.async.bulk.global.shared::cta.bulk_group.add.f32 "
                "[%0], [%1], 256;"
                :: "l"(dst), "r"(saddr) : "memory");
            asm volatile("cp.async.bulk.commit_group;" ::: "memory");
            asm volatile("red.global.add.f32 [%0], %1;"
                         :: "l"(&g_cnt[c]), "f"(1.0f) : "memory");
        }
    }
    if (lane < 4)
        asm volatile("cp.async.bulk.wait_group.read 0;" ::: "memory");
}

// ---------------------------------------------------------------------------
// Kernel 3: fused mean + GEMM + bias + relu.
//   Block = 256 threads, 64 nodes. 2 nodes per thread, 8 outputs per node.
//   Inner product uses packed fma.rn.f32x2 (half the FFMA issue slots).
// ---------------------------------------------------------------------------
#define SMEM_OUT (128 * 64 * 4 + NPB * XA_PAD * 4)

__global__ void __launch_bounds__(256) k_out(const float4* __restrict__ x4,
                                             const float*  __restrict__ W,
                                             const float*  __restrict__ b,
                                             float*        __restrict__ out) {
    extern __shared__ float sm[];
    float* sW = sm;                      // [128][64]
    float* sX = sm + 128 * 64;           // [NPB][XA_PAD]
    int tid   = threadIdx.x;
    int nbase = blockIdx.x * NPB;

    // Stage W (32KB), coalesced
    for (int i = tid; i < 128 * 64 / 4; i += 256)
        ((float4*)sW)[i] = ((const float4*)W)[i];

    // Stage x rows + mean-scaled neighbor rows (guard last partial block)
    for (int i = tid; i < NPB * 2 * DIM4; i += 256) {
        int node_l = i >> 5;             // 0..63
        int f4     = i & 31;             // 0..15 -> x, 16..31 -> neigh
        int node   = nbase + node_l;
        float4 v   = make_float4(0.f, 0.f, 0.f, 0.f);
        if (node < N_NODES) {
            if (f4 < DIM4) {
                v = x4[node * DIM4 + f4];
            } else {
                v = g_neigh4[node * DIM4 + (f4 - DIM4)];
                float inv = 1.0f / fmaxf(g_cnt[node], 1.0f);
                v.x *= inv; v.y *= inv; v.z *= inv; v.w *= inv;
            }
        }
        *(float4*)(sX + node_l * XA_PAD + f4 * 4) = v;
    }
    __syncthreads();

    int nA = tid >> 3;                   // 0..31
    int nB = nA + 32;                    // 32..63
    int jg = (tid & 7) * 8;              // output column group
    const float* xaA = sX + nA * XA_PAD;
    const float* xaB = sX + nB * XA_PAD;

    unsigned long long accA[4] = {0ULL, 0ULL, 0ULL, 0ULL};
    unsigned long long accB[4] = {0ULL, 0ULL, 0ULL, 0ULL};

    #pragma unroll 4
    for (int k = 0; k < 128; k += 4) {
        float4 aA = *(const float4*)(xaA + k);
        float4 aB = *(const float4*)(xaB + k);
        #pragma unroll
        for (int kk = 0; kk < 4; kk++) {
            const ulonglong2* wr =
                (const ulonglong2*)(sW + (k + kk) * 64 + jg);
            ulonglong2 w01 = wr[0];      // w[jg+0..3] as two f32x2
            ulonglong2 w23 = wr[1];      // w[jg+4..7]
            unsigned long long pA, pB;
            PACK2(pA, (&aA.x)[kk]);
            PACK2(pB, (&aB.x)[kk]);
            FMA2(accA[0], pA, w01.x, accA[0]);
            FMA2(accA[1], pA, w01.y, accA[1]);
            FMA2(accA[2], pA, w23.x, accA[2]);
            FMA2(accA[3], pA, w23.y, accA[3]);
            FMA2(accB[0], pB, w01.x, accB[0]);
            FMA2(accB[1], pB, w01.y, accB[1]);
            FMA2(accB[2], pB, w23.x, accB[2]);
            FMA2(accB[3], pB, w23.y, accB[3]);
        }
    }

    // bias + relu + store (unpack f32x2 pairs)
    float bias[8];
    #pragma unroll
    for (int j = 0; j < 8; j++) bias[j] = b[jg + j];

    float oA[8], oB[8];
    #pragma unroll
    for (int j = 0; j < 4; j++) {
        unsigned int lo, hi;
        asm("mov.b64 {%0, %1}, %2;" : "=r"(lo), "=r"(hi) : "l"(accA[j]));
        oA[2*j]   = __uint_as_float(lo);
        oA[2*j+1] = __uint_as_float(hi);
        asm("mov.b64 {%0, %1}, %2;" : "=r"(lo), "=r"(hi) : "l"(accB[j]));
        oB[2*j]   = __uint_as_float(lo);
        oB[2*j+1] = __uint_as_float(hi);
    }
    #pragma unroll
    for (int j = 0; j < 8; j++) {
        oA[j] = fmaxf(oA[j] + bias[j], 0.f);
        oB[j] = fmaxf(oB[j] + bias[j], 0.f);
    }

    int nodeA = nbase + nA;
    int nodeB = nbase + nB;
    if (nodeA < N_NODES) {
        *(float4*)(out + nodeA * DIM + jg)     = make_float4(oA[0], oA[1], oA[2], oA[3]);
        *(float4*)(out + nodeA * DIM + jg + 4) = make_float4(oA[4], oA[5], oA[6], oA[7]);
    }
    if (nodeB < N_NODES) {
        *(float4*)(out + nodeB * DIM + jg)     = make_float4(oB[0], oB[1], oB[2], oB[3]);
        *(float4*)(out + nodeB * DIM + jg + 4) = make_float4(oB[4], oB[5], oB[6], oB[7]);
    }
}

// ---------------------------------------------------------------------------
extern "C" void kernel_launch(void* const* d_in, const int* in_sizes, int n_in,
                              void* d_out, int out_size) {
    const float*     x  = (const float*)d_in[0];
    const long long* ei = (const long long*)d_in[1];
    const float*     W  = (const float*)d_in[2];
    const float*     b  = (const float*)d_in[3];
    float*           out = (float*)d_out;

    // 1) zero scratch + dtype probe
    k_zero<<<(N_NODES * DIM4 + 255) / 256, 256>>>(ei);

    // 2) scatter-add via TMA bulk-reduce (grid-stride over 4-edge groups)
    k_edges<<<4096, 256>>>(ei, (const float4*)x);

    // 3) fused mean + GEMM + bias + relu
    int grid = (N_NODES + NPB - 1) / NPB;   // 1563
    cudaFuncSetAttribute(k_out, cudaFuncAttributeMaxDynamicSharedMemorySize, SMEM_OUT);
    k_out<<<grid, 256, SMEM_OUT>>>((const float4*)x, W, b, out);
}

// round 7
// speedup vs baseline: 1.4666x; 1.0520x over previous
#include <cuda_runtime.h>
#include <cuda_bf16.h>
#include <cstdint>

// GraphSAGE layer: out = relu(concat(x, mean_neigh(x)) @ W + b)
// N=100000 nodes, d=64, E=1250000 edges, W [128,64], b [64], out [N,64] fp32.
//
// Strategy: build CSR-by-destination on the fly (count -> scan -> slot fill),
// then segment-sum gather with register accumulation (NO atomic feature math),
// then fused mean+GEMM+bias+relu with packed fma.rn.f32x2.

#define N_NODES 100000
#define N_EDGES 1250000
#define DIM     64
#define DIM4    16              // DIM / 4 (float4 words per row)
#define NPB     64              // nodes per block in the GEMM kernel
#define XA_PAD  132             // padded row stride (floats) for x_aggr tile
#define SCAN_BLK 98             // ceil(N_NODES / 1024)

// Scratch (static __device__; no cudaMalloc allowed)
__device__ float4 g_neigh4[N_NODES * DIM4];   // mean-aggregated neighbor feats
__device__ int    g_deg[N_NODES];
__device__ int    g_off[N_NODES];
__device__ int    g_cur[N_NODES];
__device__ int    g_src[N_EDGES];
__device__ int    g_bsum[SCAN_BLK];
__device__ int    g_boff[SCAN_BLK];
__device__ int    g_is64;

#define FMA2(d, a, b, c) \
    asm("fma.rn.f32x2 %0, %1, %2, %3;" : "=l"(d) : "l"(a), "l"(b), "l"(c))

#define PACK2(d, f) \
    asm("mov.b64 %0, {%1, %1};" : "=l"(d) : "r"(__float_as_uint(f)))

// ---------------------------------------------------------------------------
// Kernel 1: zero degree counters + detect edge_index dtype (int64 vs int32)
// ---------------------------------------------------------------------------
__global__ void k_zero(const long long* __restrict__ ei) {
    int i = blockIdx.x * blockDim.x + threadIdx.x;
    if (i < N_NODES) g_deg[i] = 0;
    if (i == 0) {
        // Probe first 4 values interpreted as int64. True int64: all in [0, N).
        bool ok = true;
        #pragma unroll
        for (int k = 0; k < 4; k++) {
            long long v = ei[k];
            if (v < 0 || v >= (long long)N_NODES) ok = false;
        }
        g_is64 = ok ? 1 : 0;
    }
}

// ---------------------------------------------------------------------------
// Kernel 2: degree histogram over destination column (RED, no return)
// ---------------------------------------------------------------------------
__global__ void __launch_bounds__(256) k_count(const long long* __restrict__ ei) {
    int i = blockIdx.x * blockDim.x + threadIdx.x;
    if (i >= N_EDGES) return;
    int c = g_is64 ? (int)ei[N_EDGES + i] : ((const int*)ei)[N_EDGES + i];
    atomicAdd(&g_deg[c], 1);
}

// ---------------------------------------------------------------------------
// Kernel 3a/3b/3c: exclusive prefix sum of g_deg -> g_off, init cursors
// ---------------------------------------------------------------------------
__global__ void __launch_bounds__(1024) k_scan1() {
    __shared__ int wsum[32];
    int i = blockIdx.x * 1024 + threadIdx.x;
    int v = (i < N_NODES) ? g_deg[i] : 0;
    int lane = threadIdx.x & 31, w = threadIdx.x >> 5;
    int s = v;
    #pragma unroll
    for (int o = 1; o < 32; o <<= 1) {
        int t = __shfl_up_sync(~0u, s, o);
        if (lane >= o) s += t;
    }
    if (lane == 31) wsum[w] = s;
    __syncthreads();
    if (w == 0) {
        int t = wsum[lane];
        #pragma unroll
        for (int o = 1; o < 32; o <<= 1) {
            int u = __shfl_up_sync(~0u, t, o);
            if (lane >= o) t += u;
        }
        wsum[lane] = t;
    }
    __syncthreads();
    int base = w ? wsum[w - 1] : 0;
    if (i < N_NODES) g_off[i] = base + s - v;       // exclusive within block
    if (threadIdx.x == 1023) g_bsum[blockIdx.x] = base + s;  // block total
}

__global__ void k_scan2() {
    if (threadIdx.x == 0) {
        int run = 0;
        for (int k = 0; k < SCAN_BLK; k++) { g_boff[k] = run; run += g_bsum[k]; }
    }
}

__global__ void __launch_bounds__(256) k_scan3() {
    int i = blockIdx.x * blockDim.x + threadIdx.x;
    if (i >= N_NODES) return;
    int o = g_off[i] + g_boff[i >> 10];
    g_off[i] = o;
    g_cur[i] = o;
}

// ---------------------------------------------------------------------------
// Kernel 4: scatter source indices into CSR slots
// ---------------------------------------------------------------------------
__global__ void __launch_bounds__(256) k_fill(const long long* __restrict__ ei) {
    int i = blockIdx.x * blockDim.x + threadIdx.x;
    if (i >= N_EDGES) return;
    int r, c;
    if (g_is64) { r = (int)ei[i]; c = (int)ei[N_EDGES + i]; }
    else        { const int* e = (const int*)ei; r = e[i]; c = e[N_EDGES + i]; }
    int slot = atomicAdd(&g_cur[c], 1);
    g_src[slot] = r;
}

// ---------------------------------------------------------------------------
// Kernel 5: segment-sum gather. One warp per destination node.
//   16 lanes cover the 64-dim row (float4 each); 2 edge streams (lane>>4),
//   combined via shfl_xor(16). Plain stores, register accumulation, fused mean.
// ---------------------------------------------------------------------------
__global__ void __launch_bounds__(256) k_aggr(const float4* __restrict__ x4) {
    int tid  = threadIdx.x;
    int lane = tid & 31;
    int d    = blockIdx.x * 8 + (tid >> 5);
    if (d >= N_NODES) return;
    int p = lane & 15;           // float4 slot within row
    int h = lane >> 4;           // edge stream 0/1

    int off = g_off[d];
    int deg = g_deg[d];
    float4 acc = make_float4(0.f, 0.f, 0.f, 0.f);

    int e   = off + h;
    int end = off + deg;
    // prefetch next src to break the src->x dependent chain
    int src = (e < end) ? g_src[e] : 0;
    for (; e < end; e += 2) {
        int src_n = (e + 2 < end) ? g_src[e + 2] : 0;
        float4 v = x4[src * DIM4 + p];
        acc.x += v.x; acc.y += v.y; acc.z += v.z; acc.w += v.w;
        src = src_n;
    }
    acc.x += __shfl_xor_sync(~0u, acc.x, 16);
    acc.y += __shfl_xor_sync(~0u, acc.y, 16);
    acc.z += __shfl_xor_sync(~0u, acc.z, 16);
    acc.w += __shfl_xor_sync(~0u, acc.w, 16);

    if (h == 0) {
        float inv = (deg > 0) ? (1.0f / (float)deg) : 0.f;
        acc.x *= inv; acc.y *= inv; acc.z *= inv; acc.w *= inv;
        g_neigh4[d * DIM4 + p] = acc;
    }
}

// ---------------------------------------------------------------------------
// Kernel 6: fused GEMM + bias + relu (f32x2 packed math).
//   Block = 256 threads, 64 nodes. 2 nodes/thread, 8 outputs/node.
// ---------------------------------------------------------------------------
#define SMEM_OUT (128 * 64 * 4 + NPB * XA_PAD * 4)

__global__ void __launch_bounds__(256) k_out(const float4* __restrict__ x4,
                                             const float*  __restrict__ W,
                                             const float*  __restrict__ b,
                                             float*        __restrict__ out) {
    extern __shared__ float sm[];
    float* sW = sm;                      // [128][64]
    float* sX = sm + 128 * 64;           // [NPB][XA_PAD]
    int tid   = threadIdx.x;
    int nbase = blockIdx.x * NPB;

    for (int i = tid; i < 128 * 64 / 4; i += 256)
        ((float4*)sW)[i] = ((const float4*)W)[i];

    for (int i = tid; i < NPB * 2 * DIM4; i += 256) {
        int node_l = i >> 5;             // 0..63
        int f4     = i & 31;             // 0..15 -> x, 16..31 -> neigh (pre-meaned)
        int node   = nbase + node_l;
        float4 v   = make_float4(0.f, 0.f, 0.f, 0.f);
        if (node < N_NODES) {
            v = (f4 < DIM4) ? x4[node * DIM4 + f4]
                            : g_neigh4[node * DIM4 + (f4 - DIM4)];
        }
        *(float4*)(sX + node_l * XA_PAD + f4 * 4) = v;
    }
    __syncthreads();

    int nA = tid >> 3;                   // 0..31
    int nB = nA + 32;                    // 32..63
    int jg = (tid & 7) * 8;
    const float* xaA = sX + nA * XA_PAD;
    const float* xaB = sX + nB * XA_PAD;

    unsigned long long accA[4] = {0ULL, 0ULL, 0ULL, 0ULL};
    unsigned long long accB[4] = {0ULL, 0ULL, 0ULL, 0ULL};

    #pragma unroll 4
    for (int k = 0; k < 128; k += 4) {
        float4 aA = *(const float4*)(xaA + k);
        float4 aB = *(const float4*)(xaB + k);
        #pragma unroll
        for (int kk = 0; kk < 4; kk++) {
            const ulonglong2* wr = (const ulonglong2*)(sW + (k + kk) * 64 + jg);
            ulonglong2 w01 = wr[0];
            ulonglong2 w23 = wr[1];
            unsigned long long pA, pB;
            PACK2(pA, (&aA.x)[kk]);
            PACK2(pB, (&aB.x)[kk]);
            FMA2(accA[0], pA, w01.x, accA[0]);
            FMA2(accA[1], pA, w01.y, accA[1]);
            FMA2(accA[2], pA, w23.x, accA[2]);
            FMA2(accA[3], pA, w23.y, accA[3]);
            FMA2(accB[0], pB, w01.x, accB[0]);
            FMA2(accB[1], pB, w01.y, accB[1]);
            FMA2(accB[2], pB, w23.x, accB[2]);
            FMA2(accB[3], pB, w23.y, accB[3]);
        }
    }

    float bias[8];
    #pragma unroll
    for (int j = 0; j < 8; j++) bias[j] = b[jg + j];

    float oA[8], oB[8];
    #pragma unroll
    for (int j = 0; j < 4; j++) {
        unsigned int lo, hi;
        asm("mov.b64 {%0, %1}, %2;" : "=r"(lo), "=r"(hi) : "l"(accA[j]));
        oA[2*j]   = __uint_as_float(lo);
        oA[2*j+1] = __uint_as_float(hi);
        asm("mov.b64 {%0, %1}, %2;" : "=r"(lo), "=r"(hi) : "l"(accB[j]));
        oB[2*j]   = __uint_as_float(lo);
        oB[2*j+1] = __uint_as_float(hi);
    }
    #pragma unroll
    for (int j = 0; j < 8; j++) {
        oA[j] = fmaxf(oA[j] + bias[j], 0.f);
        oB[j] = fmaxf(oB[j] + bias[j], 0.f);
    }

    int nodeA = nbase + nA;
    int nodeB = nbase + nB;
    if (nodeA < N_NODES) {
        *(float4*)(out + nodeA * DIM + jg)     = make_float4(oA[0], oA[1], oA[2], oA[3]);
        *(float4*)(out + nodeA * DIM + jg + 4) = make_float4(oA[4], oA[5], oA[6], oA[7]);
    }
    if (nodeB < N_NODES) {
        *(float4*)(out + nodeB * DIM + jg)     = make_float4(oB[0], oB[1], oB[2], oB[3]);
        *(float4*)(out + nodeB * DIM + jg + 4) = make_float4(oB[4], oB[5], oB[6], oB[7]);
    }
}

// ---------------------------------------------------------------------------
extern "C" void kernel_launch(void* const* d_in, const int* in_sizes, int n_in,
                              void* d_out, int out_size) {
    const float*     x  = (const float*)d_in[0];
    const long long* ei = (const long long*)d_in[1];
    const float*     W  = (const float*)d_in[2];
    const float*     b  = (const float*)d_in[3];
    float*           out = (float*)d_out;

    k_zero<<<(N_NODES + 255) / 256, 256>>>(ei);
    k_count<<<(N_EDGES + 255) / 256, 256>>>(ei);
    k_scan1<<<SCAN_BLK, 1024>>>();
    k_scan2<<<1, 32>>>();
    k_scan3<<<(N_NODES + 255) / 256, 256>>>();
    k_fill<<<(N_EDGES + 255) / 256, 256>>>(ei);
    k_aggr<<<(N_NODES + 7) / 8, 256>>>((const float4*)x);

    int grid = (N_NODES + NPB - 1) / NPB;
    cudaFuncSetAttribute(k_out, cudaFuncAttributeMaxDynamicSharedMemorySize, SMEM_OUT);
    k_out<<<grid, 256, SMEM_OUT>>>((const float4*)x, W, b, out);
}

// round 9
// speedup vs baseline: 1.8871x; 1.2868x over previous
#include <cuda_runtime.h>
#include <cuda_bf16.h>
#include <cstdint>

// GraphSAGE layer: out = relu(concat(x, mean_neigh(x)) @ W + b)
// N=100000 nodes, d=64, E=1250000 edges, W [128,64], b [64], out [N,64] fp32.
//
// CSR-by-destination (count -> scan -> fill), segment-sum gather in registers,
// fused GEMM+bias+relu with 4-node register blocking + packed fma.rn.f32x2.

#define N_NODES 100000
#define N_EDGES 1250000
#define DIM     64
#define DIM4    16              // DIM / 4 (float4 words per row)
#define NPB     128             // nodes per block in the GEMM kernel
#define XA_PAD  132             // padded row stride (floats) for x_aggr tile
#define SCAN_BLK 98             // ceil(N_NODES / 1024)

// Scratch (static __device__; no cudaMalloc allowed)
__device__ float4 g_neigh4[N_NODES * DIM4];   // mean-aggregated neighbor feats
__device__ int    g_deg[N_NODES];
__device__ int    g_off[N_NODES];             // block-LOCAL exclusive prefix
__device__ int    g_cur[N_NODES];             // cursor (starts = g_off local)
__device__ int    g_src[N_EDGES];
__device__ int    g_bsum[SCAN_BLK];
__device__ int    g_boff[SCAN_BLK];           // global offset of each 1024-chunk
__device__ int    g_is64;

#define FMA2(d, a, b, c) \
    asm("fma.rn.f32x2 %0, %1, %2, %3;" : "=l"(d) : "l"(a), "l"(b), "l"(c))

#define PACK2(d, f) \
    asm("mov.b64 %0, {%1, %1};" : "=l"(d) : "r"(__float_as_uint(f)))

// ---------------------------------------------------------------------------
// Kernel 1: zero degree counters + detect edge_index dtype (int64 vs int32)
// ---------------------------------------------------------------------------
__global__ void k_zero(const long long* __restrict__ ei) {
    int i = blockIdx.x * blockDim.x + threadIdx.x;
    if (i < N_NODES) g_deg[i] = 0;
    if (i == 0) {
        bool ok = true;
        #pragma unroll
        for (int k = 0; k < 4; k++) {
            long long v = ei[k];
            if (v < 0 || v >= (long long)N_NODES) ok = false;
        }
        g_is64 = ok ? 1 : 0;
    }
}

// ---------------------------------------------------------------------------
// Kernel 2: degree histogram over destination column (2 edges per thread)
// ---------------------------------------------------------------------------
__global__ void __launch_bounds__(256) k_count(const long long* __restrict__ ei) {
    int i = blockIdx.x * blockDim.x + threadIdx.x;   // pair index
    if (i >= N_EDGES / 2) return;
    int c0, c1;
    if (g_is64) {
        longlong2 cp = ((const longlong2*)(ei + N_EDGES))[i];
        c0 = (int)cp.x; c1 = (int)cp.y;
    } else {
        int2 cp = ((const int2*)((const int*)ei + N_EDGES))[i];
        c0 = cp.x; c1 = cp.y;
    }
    atomicAdd(&g_deg[c0], 1);
    atomicAdd(&g_deg[c1], 1);
}

// ---------------------------------------------------------------------------
// Kernel 3a: per-1024-block exclusive scan of g_deg; writes g_off (local),
//            g_cur (= local), g_bsum (block totals)
// ---------------------------------------------------------------------------
__global__ void __launch_bounds__(1024) k_scan1() {
    __shared__ int wsum[32];
    int i = blockIdx.x * 1024 + threadIdx.x;
    int v = (i < N_NODES) ? g_deg[i] : 0;
    int lane = threadIdx.x & 31, w = threadIdx.x >> 5;
    int s = v;
    #pragma unroll
    for (int o = 1; o < 32; o <<= 1) {
        int t = __shfl_up_sync(~0u, s, o);
        if (lane >= o) s += t;
    }
    if (lane == 31) wsum[w] = s;
    __syncthreads();
    if (w == 0) {
        int t = wsum[lane];
        #pragma unroll
        for (int o = 1; o < 32; o <<= 1) {
            int u = __shfl_up_sync(~0u, t, o);
            if (lane >= o) t += u;
        }
        wsum[lane] = t;
    }
    __syncthreads();
    int base = w ? wsum[w - 1] : 0;
    if (i < N_NODES) {
        int excl = base + s - v;
        g_off[i] = excl;
        g_cur[i] = excl;
    }
    if (threadIdx.x == 1023) g_bsum[blockIdx.x] = base + s;
}

// ---------------------------------------------------------------------------
// Kernel 3b: parallel scan of the 98 block sums (one warp, shfl)
// ---------------------------------------------------------------------------
__global__ void k_scan2() {
    int lane = threadIdx.x;              // 32 threads
    int base = lane * 4;
    int loc[4];
    int sum = 0;
    #pragma unroll
    for (int k = 0; k < 4; k++) {
        int idx = base + k;
        int t = (idx < SCAN_BLK) ? g_bsum[idx] : 0;
        loc[k] = sum;
        sum += t;
    }
    int run = sum;
    #pragma unroll
    for (int o = 1; o < 32; o <<= 1) {
        int t = __shfl_up_sync(~0u, run, o);
        if (lane >= o) run += t;
    }
    int excl = run - sum;
    #pragma unroll
    for (int k = 0; k < 4; k++) {
        int idx = base + k;
        if (idx < SCAN_BLK) g_boff[idx] = excl + loc[k];
    }
}

// ---------------------------------------------------------------------------
// Kernel 4: scatter source indices into CSR slots (cursor local + chunk base)
// ---------------------------------------------------------------------------
__global__ void __launch_bounds__(256) k_fill(const long long* __restrict__ ei) {
    int i = blockIdx.x * blockDim.x + threadIdx.x;
    if (i >= N_EDGES) return;
    int r, c;
    if (g_is64) { r = (int)ei[i]; c = (int)ei[N_EDGES + i]; }
    else        { const int* e = (const int*)ei; r = e[i]; c = e[N_EDGES + i]; }
    int slot = atomicAdd(&g_cur[c], 1) + g_boff[c >> 10];
    g_src[slot] = r;
}

// ---------------------------------------------------------------------------
// Kernel 5: segment-sum gather. One warp per destination node.
//   16 lanes x float4 cover the row; 2 edge streams merged via shfl_xor(16).
// ---------------------------------------------------------------------------
__global__ void __launch_bounds__(256) k_aggr(const float4* __restrict__ x4) {
    int tid  = threadIdx.x;
    int lane = tid & 31;
    int d    = blockIdx.x * 8 + (tid >> 5);
    if (d >= N_NODES) return;
    int p = lane & 15;
    int h = lane >> 4;

    int off = g_off[d] + g_boff[d >> 10];
    int deg = g_deg[d];
    float4 acc = make_float4(0.f, 0.f, 0.f, 0.f);

    int e   = off + h;
    int end = off + deg;
    int src = (e < end) ? g_src[e] : 0;
    for (; e < end; e += 2) {
        int src_n = (e + 2 < end) ? g_src[e + 2] : 0;
        float4 v = x4[src * DIM4 + p];
        acc.x += v.x; acc.y += v.y; acc.z += v.z; acc.w += v.w;
        src = src_n;
    }
    acc.x += __shfl_xor_sync(~0u, acc.x, 16);
    acc.y += __shfl_xor_sync(~0u, acc.y, 16);
    acc.z += __shfl_xor_sync(~0u, acc.z, 16);
    acc.w += __shfl_xor_sync(~0u, acc.w, 16);

    if (h == 0) {
        float inv = (deg > 0) ? (1.0f / (float)deg) : 0.f;
        acc.x *= inv; acc.y *= inv; acc.z *= inv; acc.w *= inv;
        g_neigh4[d * DIM4 + p] = acc;
    }
}

// ---------------------------------------------------------------------------
// Kernel 6: fused GEMM + bias + relu.
//   Block = 256 threads, 128 nodes. 4 nodes/thread x 8 outputs (f32x2 packed).
//   W shared-read (32B/k/thread) amortized over 4 nodes -> LDS-traffic halved.
// ---------------------------------------------------------------------------
#define SMEM_OUT (128 * 64 * 4 + NPB * XA_PAD * 4)

__global__ void __launch_bounds__(256) k_out(const float4* __restrict__ x4,
                                             const float*  __restrict__ W,
                                             const float*  __restrict__ b,
                                             float*        __restrict__ out) {
    extern __shared__ float sm[];
    float* sW = sm;                      // [128][64]
    float* sX = sm + 128 * 64;           // [NPB][XA_PAD]
    int tid   = threadIdx.x;
    int nbase = blockIdx.x * NPB;

    for (int i = tid; i < 128 * 64 / 4; i += 256)
        ((float4*)sW)[i] = ((const float4*)W)[i];

    for (int i = tid; i < NPB * 2 * DIM4; i += 256) {
        int node_l = i >> 5;             // 0..127
        int f4     = i & 31;             // 0..15 -> x, 16..31 -> neigh (pre-meaned)
        int node   = nbase + node_l;
        float4 v   = make_float4(0.f, 0.f, 0.f, 0.f);
        if (node < N_NODES) {
            v = (f4 < DIM4) ? x4[node * DIM4 + f4]
                            : g_neigh4[node * DIM4 + (f4 - DIM4)];
        }
        *(float4*)(sX + node_l * XA_PAD + f4 * 4) = v;
    }
    __syncthreads();

    int ng = tid >> 3;                   // 0..31 -> 4 nodes each
    int jg = (tid & 7) * 8;              // output column group
    const float* xa0 = sX + (ng * 4 + 0) * XA_PAD;
    const float* xa1 = sX + (ng * 4 + 1) * XA_PAD;
    const float* xa2 = sX + (ng * 4 + 2) * XA_PAD;
    const float* xa3 = sX + (ng * 4 + 3) * XA_PAD;

    unsigned long long acc[4][4];
    #pragma unroll
    for (int n = 0; n < 4; n++)
        #pragma unroll
        for (int j = 0; j < 4; j++) acc[n][j] = 0ULL;

    #pragma unroll 2
    for (int k = 0; k < 128; k += 4) {
        float4 a0 = *(const float4*)(xa0 + k);
        float4 a1 = *(const float4*)(xa1 + k);
        float4 a2 = *(const float4*)(xa2 + k);
        float4 a3 = *(const float4*)(xa3 + k);
        #pragma unroll
        for (int kk = 0; kk < 4; kk++) {
            const ulonglong2* wr = (const ulonglong2*)(sW + (k + kk) * 64 + jg);
            ulonglong2 w01 = wr[0];      // W[k][jg+0..3] as two f32x2
            ulonglong2 w23 = wr[1];      // W[k][jg+4..7]
            unsigned long long p0, p1, p2, p3;
            PACK2(p0, (&a0.x)[kk]);
            PACK2(p1, (&a1.x)[kk]);
            PACK2(p2, (&a2.x)[kk]);
            PACK2(p3, (&a3.x)[kk]);
            FMA2(acc[0][0], p0, w01.x, acc[0][0]);
            FMA2(acc[0][1], p0, w01.y, acc[0][1]);
            FMA2(acc[0][2], p0, w23.x, acc[0][2]);
            FMA2(acc[0][3], p0, w23.y, acc[0][3]);
            FMA2(acc[1][0], p1, w01.x, acc[1][0]);
            FMA2(acc[1][1], p1, w01.y, acc[1][1]);
            FMA2(acc[1][2], p1, w23.x, acc[1][2]);
            FMA2(acc[1][3], p1, w23.y, acc[1][3]);
            FMA2(acc[2][0], p2, w01.x, acc[2][0]);
            FMA2(acc[2][1], p2, w01.y, acc[2][1]);
            FMA2(acc[2][2], p2, w23.x, acc[2][2]);
            FMA2(acc[2][3], p2, w23.y, acc[2][3]);
            FMA2(acc[3][0], p3, w01.x, acc[3][0]);
            FMA2(acc[3][1], p3, w01.y, acc[3][1]);
            FMA2(acc[3][2], p3, w23.x, acc[3][2]);
            FMA2(acc[3][3], p3, w23.y, acc[3][3]);
        }
    }

    float bias[8];
    #pragma unroll
    for (int j = 0; j < 8; j++) bias[j] = b[jg + j];

    #pragma unroll
    for (int n = 0; n < 4; n++) {
        int node = nbase + ng * 4 + n;
        if (node >= N_NODES) break;
        float o[8];
        #pragma unroll
        for (int j = 0; j < 4; j++) {
            unsigned int lo, hi;
            asm("mov.b64 {%0, %1}, %2;" : "=r"(lo), "=r"(hi) : "l"(acc[n][j]));
            o[2*j]   = __uint_as_float(lo);
            o[2*j+1] = __uint_as_float(hi);
        }
        #pragma unroll
        for (int j = 0; j < 8; j++) o[j] = fmaxf(o[j] + bias[j], 0.f);
        *(float4*)(out + node * DIM + jg)     = make_float4(o[0], o[1], o[2], o[3]);
        *(float4*)(out + node * DIM + jg + 4) = make_float4(o[4], o[5], o[6], o[7]);
    }
}

// ---------------------------------------------------------------------------
extern "C" void kernel_launch(void* const* d_in, const int* in_sizes, int n_in,
                              void* d_out, int out_size) {
    const float*     x  = (const float*)d_in[0];
    const long long* ei = (const long long*)d_in[1];
    const float*     W  = (const float*)d_in[2];
    const float*     b  = (const float*)d_in[3];
    float*           out = (float*)d_out;

    k_zero<<<(N_NODES + 255) / 256, 256>>>(ei);
    k_count<<<(N_EDGES / 2 + 255) / 256, 256>>>(ei);
    k_scan1<<<SCAN_BLK, 1024>>>();
    k_scan2<<<1, 32>>>();
    k_fill<<<(N_EDGES + 255) / 256, 256>>>(ei);
    k_aggr<<<(N_NODES + 7) / 8, 256>>>((const float4*)x);

    int grid = (N_NODES + NPB - 1) / NPB;   // 782
    cudaFuncSetAttribute(k_out, cudaFuncAttributeMaxDynamicSharedMemorySize, SMEM_OUT);
    k_out<<<grid, 256, SMEM_OUT>>>((const float4*)x, W, b, out);
}

// round 12
// speedup vs baseline: 1.9454x; 1.0309x over previous
#include <cuda_runtime.h>
#include <cuda_bf16.h>
#include <cstdint>

// GraphSAGE layer: out = relu(concat(x, mean_neigh(x)) @ W + b)
// N=100000 nodes, d=64, E=1250000 edges, W [128,64], b [64], out [N,64] fp32.
//
// 5 launches: count -> scan (single-pass, spin barrier) -> fill -> aggr -> gemm.
// No atomic feature math; g_deg re-zeroed by aggr tail (replay-clean state).

#define N_NODES 100000
#define N_EDGES 1250000
#define DIM     64
#define DIM4    16              // DIM / 4 (float4 words per row)
#define NPB     128             // nodes per block in the GEMM kernel
#define XA_PAD  132             // padded row stride (floats) for x_aggr tile
#define SCAN_BLK 98             // ceil(N_NODES / 1024)

// Scratch (static __device__, zero-initialized at load; no cudaMalloc allowed)
__device__ float4 g_neigh4[N_NODES * DIM4];   // mean-aggregated neighbor feats
__device__ int    g_deg[N_NODES];             // zeroed at end of each replay
__device__ int    g_off[N_NODES];             // GLOBAL exclusive prefix
__device__ int    g_cur[N_NODES];             // fill cursors (= g_off at start)
__device__ int    g_src[N_EDGES];
__device__ int    g_bsum[SCAN_BLK];
__device__ unsigned g_arrive;                 // monotonic across replays

#define FMA2(d, a, b, c) \
    asm("fma.rn.f32x2 %0, %1, %2, %3;" : "=l"(d) : "l"(a), "l"(b), "l"(c))

#define PACK2(d, f) \
    asm("mov.b64 %0, {%1, %1};" : "=l"(d) : "r"(__float_as_uint(f)))

// dtype probe: first 4 values as int64 all in [0,N) <=> true int64 data.
// int32 data read as int64 pairs two indices -> huge value (P[false pos]~1e-20).
__device__ __forceinline__ bool detect_is64(const long long* ei) {
    bool ok = true;
    #pragma unroll
    for (int k = 0; k < 4; k++) {
        long long v = ei[k];
        if (v < 0 || v >= (long long)N_NODES) ok = false;
    }
    return ok;
}

// ---------------------------------------------------------------------------
// Kernel 1: degree histogram over destination column (2 edges per thread)
// ---------------------------------------------------------------------------
__global__ void __launch_bounds__(256) k_count(const long long* __restrict__ ei) {
    int i = blockIdx.x * blockDim.x + threadIdx.x;   // pair index
    if (i >= N_EDGES / 2) return;
    int c0, c1;
    if (detect_is64(ei)) {
        longlong2 cp = ((const longlong2*)(ei + N_EDGES))[i];
        c0 = (int)cp.x; c1 = (int)cp.y;
    } else {
        int2 cp = ((const int2*)((const int*)ei + N_EDGES))[i];
        c0 = cp.x; c1 = cp.y;
    }
    atomicAdd(&g_deg[c0], 1);
    atomicAdd(&g_deg[c1], 1);
}

// ---------------------------------------------------------------------------
// Kernel 2: single-pass exclusive scan of g_deg -> GLOBAL g_off / g_cur.
//   Per-block scan, publish block total, spin on a monotonic arrival counter
//   (all 98 blocks are co-resident: 100K threads << chip capacity), then each
//   block sums g_bsum[0..bid) with warp 0 and adds the base.
// ---------------------------------------------------------------------------
__global__ void __launch_bounds__(1024) k_scan() {
    __shared__ int wsum[32];
    __shared__ unsigned s_old;
    __shared__ int s_base;

    int i = blockIdx.x * 1024 + threadIdx.x;
    int v = (i < N_NODES) ? g_deg[i] : 0;
    int lane = threadIdx.x & 31, w = threadIdx.x >> 5;

    int s = v;
    #pragma unroll
    for (int o = 1; o < 32; o <<= 1) {
        int t = __shfl_up_sync(~0u, s, o);
        if (lane >= o) s += t;
    }
    if (lane == 31) wsum[w] = s;
    __syncthreads();
    if (w == 0) {
        int t = wsum[lane];
        #pragma unroll
        for (int o = 1; o < 32; o <<= 1) {
            int u = __shfl_up_sync(~0u, t, o);
            if (lane >= o) t += u;
        }
        wsum[lane] = t;
    }
    __syncthreads();
    int base_w = w ? wsum[w - 1] : 0;
    int excl   = base_w + s - v;         // block-local exclusive prefix

    // Publish block total + arrive (release), by the same thread.
    if (threadIdx.x == 1023) {
        g_bsum[blockIdx.x] = base_w + s;
        __threadfence();
        s_old = atomicAdd(&g_arrive, 1u);
    }
    __syncthreads();

    // Spin until all 98 blocks of THIS replay have arrived (monotonic counter).
    if (threadIdx.x == 0) {
        unsigned base = (s_old / SCAN_BLK) * SCAN_BLK;
        while ((unsigned)(atomicAdd(&g_arrive, 0u) - base) < SCAN_BLK) { }
        __threadfence();
    }
    __syncthreads();

    // Warp 0: base = sum of g_bsum[0..bid)
    if (w == 0) {
        int partial = 0;
        #pragma unroll
        for (int k = 0; k < 4; k++) {
            int idx = lane + 32 * k;
            if (idx < blockIdx.x) partial += g_bsum[idx];
        }
        #pragma unroll
        for (int o = 16; o > 0; o >>= 1)
            partial += __shfl_down_sync(~0u, partial, o);
        if (lane == 0) s_base = partial;
    }
    __syncthreads();

    if (i < N_NODES) {
        int o = s_base + excl;
        g_off[i] = o;
        g_cur[i] = o;
    }
}

// ---------------------------------------------------------------------------
// Kernel 3: scatter source indices into CSR slots (global cursors)
// ---------------------------------------------------------------------------
__global__ void __launch_bounds__(256) k_fill(const long long* __restrict__ ei) {
    int i = blockIdx.x * blockDim.x + threadIdx.x;
    if (i >= N_EDGES) return;
    int r, c;
    if (detect_is64(ei)) { r = (int)ei[i]; c = (int)ei[N_EDGES + i]; }
    else { const int* e = (const int*)ei; r = e[i]; c = e[N_EDGES + i]; }
    int slot = atomicAdd(&g_cur[c], 1);
    g_src[slot] = r;
}

// ---------------------------------------------------------------------------
// Kernel 4: segment-sum gather. One warp per destination node.
//   16 lanes x float4 cover the row; 2 edge streams (h) merged via shfl_xor(16);
//   each stream keeps 2 feature rows in flight (4 edges/warp total).
//   Tail: re-zero g_deg[d] so the next graph replay starts clean.
// ---------------------------------------------------------------------------
__global__ void __launch_bounds__(256) k_aggr(const float4* __restrict__ x4) {
    int tid  = threadIdx.x;
    int lane = tid & 31;
    int d    = blockIdx.x * 8 + (tid >> 5);
    if (d >= N_NODES) return;
    int p = lane & 15;
    int h = lane >> 4;

    int off = g_off[d];
    int deg = g_deg[d];
    int end = off + deg;
    float4 acc = make_float4(0.f, 0.f, 0.f, 0.f);

    int e  = off + h;                    // this stream: e, e+2, e+4, ...
    int s0 = (e     < end) ? g_src[e]     : 0;
    int s1 = (e + 2 < end) ? g_src[e + 2] : 0;
    while (e + 2 < end) {                // 2 stream-elements per iteration
        int n0 = (e + 4 < end) ? g_src[e + 4] : 0;
        int n1 = (e + 6 < end) ? g_src[e + 6] : 0;
        float4 v0 = x4[s0 * DIM4 + p];
        float4 v1 = x4[s1 * DIM4 + p];
        acc.x += v0.x; acc.y += v0.y; acc.z += v0.z; acc.w += v0.w;
        acc.x += v1.x; acc.y += v1.y; acc.z += v1.z; acc.w += v1.w;
        s0 = n0; s1 = n1; e += 4;
    }
    if (e < end) {                       // 0 or 1 element left in this stream
        float4 v = x4[s0 * DIM4 + p];
        acc.x += v.x; acc.y += v.y; acc.z += v.z; acc.w += v.w;
    }

    acc.x += __shfl_xor_sync(~0u, acc.x, 16);
    acc.y += __shfl_xor_sync(~0u, acc.y, 16);
    acc.z += __shfl_xor_sync(~0u, acc.z, 16);
    acc.w += __shfl_xor_sync(~0u, acc.w, 16);

    if (h == 0) {
        float inv = (deg > 0) ? (1.0f / (float)deg) : 0.f;
        acc.x *= inv; acc.y *= inv; acc.z *= inv; acc.w *= inv;
        g_neigh4[d * DIM4 + p] = acc;
        if (p == 0) g_deg[d] = 0;        // leave clean state for next replay
    }
}

// ---------------------------------------------------------------------------
// Kernel 5: fused GEMM + bias + relu.
//   Block = 256 threads, 128 nodes. 4 nodes/thread x 8 outputs (f32x2 packed).
// ---------------------------------------------------------------------------
#define SMEM_OUT (128 * 64 * 4 + NPB * XA_PAD * 4)

__global__ void __launch_bounds__(256) k_out(const float4* __restrict__ x4,
                                             const float*  __restrict__ W,
                                             const float*  __restrict__ b,
                                             float*        __restrict__ out) {
    extern __shared__ float sm[];
    float* sW = sm;                      // [128][64]
    float* sX = sm + 128 * 64;           // [NPB][XA_PAD]
    int tid   = threadIdx.x;
    int nbase = blockIdx.x * NPB;

    for (int i = tid; i < 128 * 64 / 4; i += 256)
        ((float4*)sW)[i] = ((const float4*)W)[i];

    for (int i = tid; i < NPB * 2 * DIM4; i += 256) {
        int node_l = i >> 5;             // 0..127
        int f4     = i & 31;             // 0..15 -> x, 16..31 -> neigh (pre-meaned)
        int node   = nbase + node_l;
        float4 v   = make_float4(0.f, 0.f, 0.f, 0.f);
        if (node < N_NODES) {
            v = (f4 < DIM4) ? x4[node * DIM4 + f4]
                            : g_neigh4[node * DIM4 + (f4 - DIM4)];
        }
        *(float4*)(sX + node_l * XA_PAD + f4 * 4) = v;
    }
    __syncthreads();

    int ng = tid >> 3;                   // 0..31 -> 4 nodes each
    int jg = (tid & 7) * 8;              // output column group
    const float* xa0 = sX + (ng * 4 + 0) * XA_PAD;
    const float* xa1 = sX + (ng * 4 + 1) * XA_PAD;
    const float* xa2 = sX + (ng * 4 + 2) * XA_PAD;
    const float* xa3 = sX + (ng * 4 + 3) * XA_PAD;

    unsigned long long acc[4][4];
    #pragma unroll
    for (int n = 0; n < 4; n++)
        #pragma unroll
        for (int j = 0; j < 4; j++) acc[n][j] = 0ULL;

    #pragma unroll 2
    for (int k = 0; k < 128; k += 4) {
        float4 a0 = *(const float4*)(xa0 + k);
        float4 a1 = *(const float4*)(xa1 + k);
        float4 a2 = *(const float4*)(xa2 + k);
        float4 a3 = *(const float4*)(xa3 + k);
        #pragma unroll
        for (int kk = 0; kk < 4; kk++) {
            const ulonglong2* wr = (const ulonglong2*)(sW + (k + kk) * 64 + jg);
            ulonglong2 w01 = wr[0];      // W[k][jg+0..3] as two f32x2
            ulonglong2 w23 = wr[1];      // W[k][jg+4..7]
            unsigned long long p0, p1, p2, p3;
            PACK2(p0, (&a0.x)[kk]);
            PACK2(p1, (&a1.x)[kk]);
            PACK2(p2, (&a2.x)[kk]);
            PACK2(p3, (&a3.x)[kk]);
            FMA2(acc[0][0], p0, w01.x, acc[0][0]);
            FMA2(acc[0][1], p0, w01.y, acc[0][1]);
            FMA2(acc[0][2], p0, w23.x, acc[0][2]);
            FMA2(acc[0][3], p0, w23.y, acc[0][3]);
            FMA2(acc[1][0], p1, w01.x, acc[1][0]);
            FMA2(acc[1][1], p1, w01.y, acc[1][1]);
            FMA2(acc[1][2], p1, w23.x, acc[1][2]);
            FMA2(acc[1][3], p1, w23.y, acc[1][3]);
            FMA2(acc[2][0], p2, w01.x, acc[2][0]);
            FMA2(acc[2][1], p2, w01.y, acc[2][1]);
            FMA2(acc[2][2], p2, w23.x, acc[2][2]);
            FMA2(acc[2][3], p2, w23.y, acc[2][3]);
            FMA2(acc[3][0], p3, w01.x, acc[3][0]);
            FMA2(acc[3][1], p3, w01.y, acc[3][1]);
            FMA2(acc[3][2], p3, w23.x, acc[3][2]);
            FMA2(acc[3][3], p3, w23.y, acc[3][3]);
        }
    }

    float bias[8];
    #pragma unroll
    for (int j = 0; j < 8; j++) bias[j] = b[jg + j];

    #pragma unroll
    for (int n = 0; n < 4; n++) {
        int node = nbase + ng * 4 + n;
        if (node >= N_NODES) break;
        float o[8];
        #pragma unroll
        for (int j = 0; j < 4; j++) {
            unsigned int lo, hi;
            asm("mov.b64 {%0, %1}, %2;" : "=r"(lo), "=r"(hi) : "l"(acc[n][j]));
            o[2*j]   = __uint_as_float(lo);
            o[2*j+1] = __uint_as_float(hi);
        }
        #pragma unroll
        for (int j = 0; j < 8; j++) o[j] = fmaxf(o[j] + bias[j], 0.f);
        *(float4*)(out + node * DIM + jg)     = make_float4(o[0], o[1], o[2], o[3]);
        *(float4*)(out + node * DIM + jg + 4) = make_float4(o[4], o[5], o[6], o[7]);
    }
}

// ---------------------------------------------------------------------------
extern "C" void kernel_launch(void* const* d_in, const int* in_sizes, int n_in,
                              void* d_out, int out_size) {
    const float*     x  = (const float*)d_in[0];
    const long long* ei = (const long long*)d_in[1];
    const float*     W  = (const float*)d_in[2];
    const float*     b  = (const float*)d_in[3];
    float*           out = (float*)d_out;

    k_count<<<(N_EDGES / 2 + 255) / 256, 256>>>(ei);
    k_scan<<<SCAN_BLK, 1024>>>();
    k_fill<<<(N_EDGES + 255) / 256, 256>>>(ei);
    k_aggr<<<(N_NODES + 7) / 8, 256>>>((const float4*)x);

    int grid = (N_NODES + NPB - 1) / NPB;   // 782
    cudaFuncSetAttribute(k_out, cudaFuncAttributeMaxDynamicSharedMemorySize, SMEM_OUT);
    k_out<<<grid, 256, SMEM_OUT>>>((const float4*)x, W, b, out);
}